// round 1
// baseline (speedup 1.0000x reference)
#include <cuda_runtime.h>
#include <cuda_bf16.h>
#include <math.h>

// Problem shapes (fixed by the reference)
#define BB 4
#define SS 4096
#define UU 1024

// Scratch (allocation-free rule: __device__ globals)
__device__ float g_pq[BB * SS * UU];
__device__ float g_pk[BB * SS * UU];
__device__ float g_pv[BB * SS * UU];
__device__ float g_kv[BB * UU * UU];
__device__ float g_o1[BB * SS * UU];

// ---------------- packed f32x2 helpers (Blackwell FFMA2 path) ----------------
__device__ __forceinline__ unsigned long long pack2(float lo, float hi) {
    unsigned long long r;
    asm("mov.b64 %0, {%1, %2};" : "=l"(r) : "f"(lo), "f"(hi));
    return r;
}
__device__ __forceinline__ void unpack2(unsigned long long v, float& lo, float& hi) {
    asm("mov.b64 {%0, %1}, %2;" : "=f"(lo), "=f"(hi) : "l"(v));
}
__device__ __forceinline__ unsigned long long ffma2(unsigned long long a,
                                                    unsigned long long b,
                                                    unsigned long long c) {
    unsigned long long d;
    asm("fma.rn.f32x2 %0, %1, %2, %3;" : "=l"(d) : "l"(a), "l"(b), "l"(c));
    return d;
}

// ---------------- tiled GEMM ----------------
// C[M,N] = A ? B  (row-major). If TRANSA == false: A is [M,K] (lda=K).
// If TRANSA == true:  A is [K,M] (lda=M), i.e. C = A^T B.
// B is [K,N] (ldb=N). Batched via blockIdx.z with element strides sA/sB/sC.
// mode: 0 = plain store, 1 = *mask[row], 2 = *mask[row] then swish.
#define BM 128
#define BN 128
#define BK 16
#define TM 8
#define TN 8
#define NTHREADS 256
#define LDS_PAD 4
#define LDA_S (BM + LDS_PAD)

template <bool TRANSA>
__global__ __launch_bounds__(NTHREADS, 2)
void gemm_kernel(const float* __restrict__ A, const float* __restrict__ B,
                 float* __restrict__ C, int M, int N, int K,
                 long long sA, long long sB, long long sC,
                 const float* __restrict__ mask, int mode) {
    __shared__ float As[BK][LDA_S];
    __shared__ float Bs[BK][BN + LDS_PAD];

    const int bz = blockIdx.z;
    A += (long long)bz * sA;
    B += (long long)bz * sB;
    C += (long long)bz * sC;

    const int m0 = blockIdx.y * BM;
    const int n0 = blockIdx.x * BN;
    const int tid = threadIdx.x;
    const int tm = (tid >> 4) * TM;   // 16 thread-rows
    const int tn = (tid & 15) * TN;   // 16 thread-cols

    unsigned long long acc[TM][TN / 2];
#pragma unroll
    for (int i = 0; i < TM; i++)
#pragma unroll
        for (int j = 0; j < TN / 2; j++) acc[i][j] = 0ull;

    for (int k0 = 0; k0 < K; k0 += BK) {
        // ---- load A tile into As[k][m] ----
        if (TRANSA) {
            // A is [K, M]: rows k0..k0+15, cols m0..m0+127 (contiguous) -> direct
#pragma unroll
            for (int it = 0; it < 2; ++it) {
                int idx = tid + it * NTHREADS;        // 0..511 float4s
                int r = idx >> 5;                     // 0..15
                int c = (idx & 31) << 2;              // 0..124
                float4 v = *reinterpret_cast<const float4*>(
                    A + (long long)(k0 + r) * M + m0 + c);
                *reinterpret_cast<float4*>(&As[r][c]) = v;
            }
        } else {
            // A is [M, K]: rows m0..m0+127, cols k0..k0+15 -> transpose into As
#pragma unroll
            for (int it = 0; it < 2; ++it) {
                int idx = tid + it * NTHREADS;        // 0..511 float4s
                int row = idx >> 2;                   // 0..127
                int c4 = (idx & 3) << 2;              // 0,4,8,12
                float4 v = *reinterpret_cast<const float4*>(
                    A + (long long)(m0 + row) * K + k0 + c4);
                As[c4 + 0][row] = v.x;
                As[c4 + 1][row] = v.y;
                As[c4 + 2][row] = v.z;
                As[c4 + 3][row] = v.w;
            }
        }
        // ---- load B tile into Bs[k][n] ----
#pragma unroll
        for (int it = 0; it < 2; ++it) {
            int idx = tid + it * NTHREADS;
            int r = idx >> 5;
            int c = (idx & 31) << 2;
            float4 v = *reinterpret_cast<const float4*>(
                B + (long long)(k0 + r) * N + n0 + c);
            *reinterpret_cast<float4*>(&Bs[r][c]) = v;
        }
        __syncthreads();

#pragma unroll
        for (int k = 0; k < BK; ++k) {
            float4 b0 = *reinterpret_cast<const float4*>(&Bs[k][tn]);
            float4 b1 = *reinterpret_cast<const float4*>(&Bs[k][tn + 4]);
            unsigned long long bb[4];
            bb[0] = pack2(b0.x, b0.y);
            bb[1] = pack2(b0.z, b0.w);
            bb[2] = pack2(b1.x, b1.y);
            bb[3] = pack2(b1.z, b1.w);
            float4 a0 = *reinterpret_cast<const float4*>(&As[k][tm]);
            float4 a1 = *reinterpret_cast<const float4*>(&As[k][tm + 4]);
            float a[TM] = {a0.x, a0.y, a0.z, a0.w, a1.x, a1.y, a1.z, a1.w};
#pragma unroll
            for (int i = 0; i < TM; i++) {
                unsigned long long ad = pack2(a[i], a[i]);
#pragma unroll
                for (int j = 0; j < TN / 2; j++)
                    acc[i][j] = ffma2(ad, bb[j], acc[i][j]);
            }
        }
        __syncthreads();
    }

    // ---- epilogue ----
#pragma unroll
    for (int i = 0; i < TM; i++) {
        int row = m0 + tm + i;
        float o[TN];
#pragma unroll
        for (int j = 0; j < TN / 2; j++) unpack2(acc[i][j], o[2 * j], o[2 * j + 1]);
        if (mode > 0) {
            float mv = mask[row];
#pragma unroll
            for (int j = 0; j < TN; j++) o[j] *= mv;
        }
        if (mode == 2) {
#pragma unroll
            for (int j = 0; j < TN; j++) o[j] = o[j] / (1.0f + expf(-o[j]));
        }
        float4 r0 = make_float4(o[0], o[1], o[2], o[3]);
        float4 r1 = make_float4(o[4], o[5], o[6], o[7]);
        float* cp = C + (long long)row * N + n0 + tn;
        *reinterpret_cast<float4*>(cp) = r0;
        *reinterpret_cast<float4*>(cp + 4) = r1;
    }
}

extern "C" void kernel_launch(void* const* d_in, const int* in_sizes, int n_in,
                              void* d_out, int out_size) {
    const float* query = (const float*)d_in[0];
    const float* key   = (const float*)d_in[1];
    const float* value = (const float*)d_in[2];
    const float* mask  = (const float*)d_in[3];
    const float* Wk    = (const float*)d_in[4];
    const float* Wv    = (const float*)d_in[5];
    const float* Wq    = (const float*)d_in[6];
    const float* Wo    = (const float*)d_in[7];
    float* out = (float*)d_out;

    float *pq, *pk, *pv, *kv, *o1;
    cudaGetSymbolAddress((void**)&pq, g_pq);
    cudaGetSymbolAddress((void**)&pk, g_pk);
    cudaGetSymbolAddress((void**)&pv, g_pv);
    cudaGetSymbolAddress((void**)&kv, g_kv);
    cudaGetSymbolAddress((void**)&o1, g_o1);

    const int M1 = BB * SS;  // 16384
    dim3 block(NTHREADS);

    // 1) projections: [16384,1024] x [1024,1024]
    dim3 gProj(UU / BN, M1 / BM, 1);
    gemm_kernel<false><<<gProj, block>>>(query, Wq, pq, M1, UU, UU, 0, 0, 0, nullptr, 0);
    gemm_kernel<false><<<gProj, block>>>(key,   Wk, pk, M1, UU, UU, 0, 0, 0, mask, 2);  // mask then swish
    gemm_kernel<false><<<gProj, block>>>(value, Wv, pv, M1, UU, UU, 0, 0, 0, mask, 1);  // mask

    // 2) kv[b] = pk[b]^T @ pv[b]  : [1024,1024] per batch, K=4096
    dim3 gKV(UU / BN, UU / BM, BB);
    gemm_kernel<true><<<gKV, block>>>(pk, pv, kv, UU, UU, SS,
                                      (long long)SS * UU, (long long)SS * UU,
                                      (long long)UU * UU, nullptr, 0);

    // 3) o1[b] = pq[b] @ kv[b] : [4096,1024] per batch, K=1024
    dim3 gQKV(UU / BN, SS / BM, BB);
    gemm_kernel<false><<<gQKV, block>>>(pq, kv, o1, SS, UU, UU,
                                        (long long)SS * UU, (long long)UU * UU,
                                        (long long)SS * UU, nullptr, 0);

    // 4) out = o1 @ Wo : [16384,1024]
    gemm_kernel<false><<<gProj, block>>>(o1, Wo, out, M1, UU, UU, 0, 0, 0, nullptr, 0);
}